// round 13
// baseline (speedup 1.0000x reference)
#include <cuda_runtime.h>
#include <cuda_fp16.h>
#include <math.h>

#define NN   100000
#define NN4  (NN / 4)        // 25000
#define CONV 16
#define HIDD 1024
#define OUTD 256

// ---------------- device scratch (no allocations allowed) ----------------
__device__ __align__(16) float  g_degf[NN];
__device__ __align__(16) float  g_dinv[NN];
__device__ __align__(16) float  g_s1[NN];      // conv1 accumulator (fp32 atomics)
__device__ __align__(16) __half g_xnh[NN];     // x[i]*dinv[i] as fp16 (L1-resident gathers)
__device__ __align__(16) float  g_s2[NN];      // conv2 accumulator
__device__ __align__(16) __half g_hhnh[NN];    // hh[i]*dinv[i] as fp16
__device__ __align__(16) float  g_v[NN];       // final node scalar
__device__ __align__(16) float  g_z[HIDD];     // hidden layer (post-lrelu)
__device__ __align__(16) float  g_logits[OUTD];
__device__ unsigned g_fc2cnt;                  // reset each run in node3

__device__ __forceinline__ float lrelu(float x) {
    return x >= 0.0f ? x : 0.01f * x;
}

__device__ __forceinline__ unsigned h2_as_u32(__half2 h) {
    return *reinterpret_cast<unsigned*>(&h);
}

// ---------------- node kernels (4 nodes per thread) ----------------
__global__ void k_node1(const float4* __restrict__ x4) {
    int i = blockIdx.x * blockDim.x + threadIdx.x;
    if (i < NN4) {
        float4 dg = ((const float4*)g_degf)[i];
        float4 xv = __ldg(&x4[i]);
        float d0 = rsqrtf(dg.x + 1.0f);
        float d1 = rsqrtf(dg.y + 1.0f);
        float d2 = rsqrtf(dg.z + 1.0f);
        float d3 = rsqrtf(dg.w + 1.0f);
        ((float4*)g_dinv)[i] = make_float4(d0, d1, d2, d3);
        float xn0 = xv.x * d0, xn1 = xv.y * d1, xn2 = xv.z * d2, xn3 = xv.w * d3;
        __half2 h01 = __floats2half2_rn(xn0, xn1);
        __half2 h23 = __floats2half2_rn(xn2, xn3);
        ((uint2*)g_xnh)[i] = make_uint2(h2_as_u32(h01), h2_as_u32(h23));
        ((float4*)g_s1)[i] = make_float4(xn0 * d0, xn1 * d1, xn2 * d2, xn3 * d3);
    }
}

__global__ void k_node2(const float* __restrict__ W1c,
                        const float* __restrict__ b1c,
                        const float* __restrict__ W2c) {
    int i = blockIdx.x * blockDim.x + threadIdx.x;
    if (i < NN4) {
        float4 dv = ((const float4*)g_dinv)[i];
        float4 s1 = ((const float4*)g_s1)[i];
        float a[4] = { dv.x * s1.x, dv.y * s1.y, dv.z * s1.z, dv.w * s1.w };
        float hh[4] = { 0.f, 0.f, 0.f, 0.f };
#pragma unroll
        for (int c = 0; c < CONV; c++) {
            float w1 = __ldg(&W1c[c]);
            float bb = __ldg(&b1c[c]);
            float w2 = __ldg(&W2c[c]);
#pragma unroll
            for (int j = 0; j < 4; j++) {
                float t = lrelu(fmaf(a[j], w1, bb));
                hh[j] = fmaf(t, w2, hh[j]);
            }
        }
        float hn0 = hh[0] * dv.x, hn1 = hh[1] * dv.y;
        float hn2 = hh[2] * dv.z, hn3 = hh[3] * dv.w;
        __half2 h01 = __floats2half2_rn(hn0, hn1);
        __half2 h23 = __floats2half2_rn(hn2, hn3);
        ((uint2*)g_hhnh)[i] = make_uint2(h2_as_u32(h01), h2_as_u32(h23));
        ((float4*)g_s2)[i] = make_float4(hn0 * dv.x, hn1 * dv.y, hn2 * dv.z, hn3 * dv.w);
    }
}

__global__ void k_node3(const float* __restrict__ b2c) {
    int i = blockIdx.x * blockDim.x + threadIdx.x;
    if (i == 0) g_fc2cnt = 0;   // reset fc2 completion counter each run
    if (i < NN4) {
        float b = __ldg(&b2c[0]);
        float4 dv = ((const float4*)g_dinv)[i];
        float4 s2 = ((const float4*)g_s2)[i];
        ((float4*)g_v)[i] = make_float4(
            lrelu(fmaf(dv.x, s2.x, b)),
            lrelu(fmaf(dv.y, s2.y, b)),
            lrelu(fmaf(dv.z, s2.z, b)),
            lrelu(fmaf(dv.w, s2.w, b)));
    }
}

// ---------------- edge kernels: 4 edges per thread via int4 ----------------
__global__ void k_deg(const int4* __restrict__ dst4, int E4) {
    int e = blockIdx.x * blockDim.x + threadIdx.x;
    if (e < E4) {
        int4 d = __ldcs(&dst4[e]);
        if ((unsigned)d.x < (unsigned)NN) atomicAdd(&g_degf[d.x], 1.0f);
        if ((unsigned)d.y < (unsigned)NN) atomicAdd(&g_degf[d.y], 1.0f);
        if ((unsigned)d.z < (unsigned)NN) atomicAdd(&g_degf[d.z], 1.0f);
        if ((unsigned)d.w < (unsigned)NN) atomicAdd(&g_degf[d.w], 1.0f);
    }
}

__global__ void k_scatter1(const int4* __restrict__ src4,
                           const int4* __restrict__ dst4, int E4) {
    int e = blockIdx.x * blockDim.x + threadIdx.x;
    if (e < E4) {
        int4 s = __ldcs(&src4[e]);
        int4 d = __ldcs(&dst4[e]);
        float vx = __half2float(g_xnh[s.x]);
        float vy = __half2float(g_xnh[s.y]);
        float vz = __half2float(g_xnh[s.z]);
        float vw = __half2float(g_xnh[s.w]);
        if ((unsigned)d.x < (unsigned)NN) atomicAdd(&g_s1[d.x], vx);
        if ((unsigned)d.y < (unsigned)NN) atomicAdd(&g_s1[d.y], vy);
        if ((unsigned)d.z < (unsigned)NN) atomicAdd(&g_s1[d.z], vz);
        if ((unsigned)d.w < (unsigned)NN) atomicAdd(&g_s1[d.w], vw);
    }
}

__global__ void k_scatter2(const int4* __restrict__ src4,
                           const int4* __restrict__ dst4, int E4) {
    int e = blockIdx.x * blockDim.x + threadIdx.x;
    if (e < E4) {
        int4 s = __ldcs(&src4[e]);
        int4 d = __ldcs(&dst4[e]);
        float vx = __half2float(g_hhnh[s.x]);
        float vy = __half2float(g_hhnh[s.y]);
        float vz = __half2float(g_hhnh[s.z]);
        float vw = __half2float(g_hhnh[s.w]);
        if ((unsigned)d.x < (unsigned)NN) atomicAdd(&g_s2[d.x], vx);
        if ((unsigned)d.y < (unsigned)NN) atomicAdd(&g_s2[d.y], vy);
        if ((unsigned)d.z < (unsigned)NN) atomicAdd(&g_s2[d.z], vz);
        if ((unsigned)d.w < (unsigned)NN) atomicAdd(&g_s2[d.w], vw);
    }
}

// ---------------- GEMV: 4 rows per block, 512 threads ----------------
__global__ void k_gemv(const float* __restrict__ Wf1,
                       const float* __restrict__ bf1) {
    const int r0 = blockIdx.x * 4;
    const int tid = threadIdx.x;     // 512 threads
    const float4* __restrict__ rowA = (const float4*)(Wf1 + (size_t)(r0 + 0) * NN);
    const float4* __restrict__ rowB = (const float4*)(Wf1 + (size_t)(r0 + 1) * NN);
    const float4* __restrict__ rowC = (const float4*)(Wf1 + (size_t)(r0 + 2) * NN);
    const float4* __restrict__ rowD = (const float4*)(Wf1 + (size_t)(r0 + 3) * NN);
    const float4* __restrict__ vv   = (const float4*)g_v;

    float sa = 0.f, sb = 0.f, sc = 0.f, sd = 0.f;
    for (int i = tid; i < NN4; i += 512) {
        float4 x  = vv[i];
        float4 wA = __ldcs(&rowA[i]);
        float4 wB = __ldcs(&rowB[i]);
        float4 wC = __ldcs(&rowC[i]);
        float4 wD = __ldcs(&rowD[i]);
        sa += wA.x*x.x + wA.y*x.y + wA.z*x.z + wA.w*x.w;
        sb += wB.x*x.x + wB.y*x.y + wB.z*x.z + wB.w*x.w;
        sc += wC.x*x.x + wC.y*x.y + wC.z*x.z + wC.w*x.w;
        sd += wD.x*x.x + wD.y*x.y + wD.z*x.z + wD.w*x.w;
    }

#pragma unroll
    for (int o = 16; o > 0; o >>= 1) {
        sa += __shfl_down_sync(0xFFFFFFFFu, sa, o);
        sb += __shfl_down_sync(0xFFFFFFFFu, sb, o);
        sc += __shfl_down_sync(0xFFFFFFFFu, sc, o);
        sd += __shfl_down_sync(0xFFFFFFFFu, sd, o);
    }
    __shared__ float redA[16], redB[16], redC[16], redD[16];
    int lane = tid & 31, wid = tid >> 5;   // 16 warps
    if (lane == 0) { redA[wid] = sa; redB[wid] = sb; redC[wid] = sc; redD[wid] = sd; }
    __syncthreads();
    if (wid == 0) {
        sa = (lane < 16) ? redA[lane] : 0.0f;
        sb = (lane < 16) ? redB[lane] : 0.0f;
        sc = (lane < 16) ? redC[lane] : 0.0f;
        sd = (lane < 16) ? redD[lane] : 0.0f;
#pragma unroll
        for (int o = 8; o > 0; o >>= 1) {
            sa += __shfl_down_sync(0xFFFFFFFFu, sa, o);
            sb += __shfl_down_sync(0xFFFFFFFFu, sb, o);
            sc += __shfl_down_sync(0xFFFFFFFFu, sc, o);
            sd += __shfl_down_sync(0xFFFFFFFFu, sd, o);
        }
        if (lane == 0) {
            g_z[r0 + 0] = lrelu(sa + __ldg(&bf1[r0 + 0]));
            g_z[r0 + 1] = lrelu(sb + __ldg(&bf1[r0 + 1]));
            g_z[r0 + 2] = lrelu(sc + __ldg(&bf1[r0 + 2]));
            g_z[r0 + 3] = lrelu(sd + __ldg(&bf1[r0 + 3]));
        }
    }
}

// ---------------- FC2 + fused log_softmax (last-block completes) ----------------
__global__ void k_fc2(const float* __restrict__ Wf2,
                      const float* __restrict__ bf2,
                      float* __restrict__ out) {
    const int o = blockIdx.x;          // 0..255
    const int tid = threadIdx.x;       // 128 threads
    const float4* __restrict__ row = (const float4*)(Wf2 + (size_t)o * HIDD);
    const float4* __restrict__ zz  = (const float4*)g_z;
    float s = 0.0f;
#pragma unroll
    for (int i = tid; i < HIDD / 4; i += 128) {   // 2 iterations
        float4 w = __ldg(&row[i]);
        float4 z = zz[i];
        s += w.x*z.x + w.y*z.y + w.z*z.z + w.w*z.w;
    }
#pragma unroll
    for (int off = 16; off > 0; off >>= 1)
        s += __shfl_down_sync(0xFFFFFFFFu, s, off);
    __shared__ float red[4];
    int lane = tid & 31, wid = tid >> 5;
    if (lane == 0) red[wid] = s;
    __syncthreads();
    __shared__ bool last;
    if (tid == 0) {
        float t = red[0] + red[1] + red[2] + red[3];
        g_logits[o] = t + __ldg(&bf2[o]);
        __threadfence();
        unsigned done = atomicAdd(&g_fc2cnt, 1u);
        last = (done == (unsigned)(gridDim.x - 1));
    }
    __syncthreads();
    if (!last) return;

    // ---- last block: log_softmax over 256 logits with 128 threads ----
    __shared__ float buf[128];
    float a0 = g_logits[tid];
    float a1 = g_logits[tid + 128];
    float m = fmaxf(a0, a1);
    buf[tid] = m;
    __syncthreads();
#pragma unroll
    for (int off = 64; off > 0; off >>= 1) {
        if (tid < off) buf[tid] = fmaxf(buf[tid], buf[tid + off]);
        __syncthreads();
    }
    float mx = buf[0];
    __syncthreads();
    buf[tid] = expf(a0 - mx) + expf(a1 - mx);
    __syncthreads();
#pragma unroll
    for (int off = 64; off > 0; off >>= 1) {
        if (tid < off) buf[tid] += buf[tid + off];
        __syncthreads();
    }
    float lse = mx + logf(buf[0]);
    out[tid]       = a0 - lse;
    out[tid + 128] = a1 - lse;
}

// ---------------- launch ----------------
extern "C" void kernel_launch(void* const* d_in, const int* in_sizes, int n_in,
                              void* d_out, int out_size) {
    const float* x   = (const float*)d_in[0];
    const int*   ei  = (const int*)d_in[1];     // int32 (jax downcast)
    const float* W1c = (const float*)d_in[2];
    const float* b1c = (const float*)d_in[3];
    const float* W2c = (const float*)d_in[4];
    const float* b2c = (const float*)d_in[5];
    const float* Wf1 = (const float*)d_in[6];
    const float* bf1 = (const float*)d_in[7];
    const float* Wf2 = (const float*)d_in[8];
    const float* bf2 = (const float*)d_in[9];
    float* out = (float*)d_out;

    const int E = in_sizes[1] / 2;              // 3,200,000
    const int E4 = E / 4;                       // 800,000
    const int4* src4 = (const int4*)ei;
    const int4* dst4 = (const int4*)(ei + E);

    const int TB = 256;
    const int nb_node4 = (NN4 + TB - 1) / TB;   // 98
    const int nb_edge4 = (E4 + TB - 1) / TB;

    // zero degrees via captured memset (no kernel launch)
    void* degp = nullptr;
    cudaGetSymbolAddress(&degp, g_degf);
    cudaMemsetAsync(degp, 0, NN * sizeof(float));

    k_deg<<<nb_edge4, TB>>>(dst4, E4);
    k_node1<<<nb_node4, TB>>>((const float4*)x);
    k_scatter1<<<nb_edge4, TB>>>(src4, dst4, E4);
    k_node2<<<nb_node4, TB>>>(W1c, b1c, W2c);
    k_scatter2<<<nb_edge4, TB>>>(src4, dst4, E4);
    k_node3<<<nb_node4, TB>>>(b2c);
    k_gemv<<<HIDD / 4, 512>>>(Wf1, bf1);
    k_fc2<<<OUTD, 128>>>(Wf2, bf2, out);
}

// round 14
// speedup vs baseline: 1.0079x; 1.0079x over previous
#include <cuda_runtime.h>
#include <cuda_fp16.h>
#include <math.h>

#define NN   100000
#define NN4  (NN / 4)        // 25000
#define CONV 16
#define HIDD 1024
#define OUTD 256

// ---------------- device scratch (no allocations allowed) ----------------
__device__ __align__(16) float  g_degf[NN];
__device__ __align__(16) float  g_dinv[NN];
__device__ __align__(16) float  g_s1[NN];      // conv1 accumulator (fp32 atomics)
__device__ __align__(16) __half g_xnh[NN];     // x[i]*dinv[i] as fp16 (L1-resident gathers)
__device__ __align__(16) float  g_s2[NN];      // conv2 accumulator
__device__ __align__(16) __half g_hhnh[NN];    // hh[i]*dinv[i] as fp16
__device__ __align__(16) float  g_v[NN];       // final node scalar
__device__ __align__(16) float  g_z[HIDD];     // hidden layer (post-lrelu)
__device__ __align__(16) float  g_logits[OUTD];
__device__ unsigned g_fc2cnt;                  // reset each run in node3

__device__ __forceinline__ float lrelu(float x) {
    return x >= 0.0f ? x : 0.01f * x;
}

__device__ __forceinline__ unsigned h2_as_u32(__half2 h) {
    return *reinterpret_cast<unsigned*>(&h);
}

// ---------------- node kernels (4 nodes per thread) ----------------
__global__ void k_node1(const float4* __restrict__ x4) {
    int i = blockIdx.x * blockDim.x + threadIdx.x;
    if (i < NN4) {
        float4 dg = ((const float4*)g_degf)[i];
        float4 xv = __ldg(&x4[i]);
        float d0 = rsqrtf(dg.x + 1.0f);
        float d1 = rsqrtf(dg.y + 1.0f);
        float d2 = rsqrtf(dg.z + 1.0f);
        float d3 = rsqrtf(dg.w + 1.0f);
        ((float4*)g_dinv)[i] = make_float4(d0, d1, d2, d3);
        float xn0 = xv.x * d0, xn1 = xv.y * d1, xn2 = xv.z * d2, xn3 = xv.w * d3;
        __half2 h01 = __floats2half2_rn(xn0, xn1);
        __half2 h23 = __floats2half2_rn(xn2, xn3);
        ((uint2*)g_xnh)[i] = make_uint2(h2_as_u32(h01), h2_as_u32(h23));
        ((float4*)g_s1)[i] = make_float4(xn0 * d0, xn1 * d1, xn2 * d2, xn3 * d3);
    }
}

__global__ void k_node2(const float* __restrict__ W1c,
                        const float* __restrict__ b1c,
                        const float* __restrict__ W2c) {
    int i = blockIdx.x * blockDim.x + threadIdx.x;
    if (i < NN4) {
        float4 dv = ((const float4*)g_dinv)[i];
        float4 s1 = ((const float4*)g_s1)[i];
        float a[4] = { dv.x * s1.x, dv.y * s1.y, dv.z * s1.z, dv.w * s1.w };
        float hh[4] = { 0.f, 0.f, 0.f, 0.f };
#pragma unroll
        for (int c = 0; c < CONV; c++) {
            float w1 = __ldg(&W1c[c]);
            float bb = __ldg(&b1c[c]);
            float w2 = __ldg(&W2c[c]);
#pragma unroll
            for (int j = 0; j < 4; j++) {
                float t = lrelu(fmaf(a[j], w1, bb));
                hh[j] = fmaf(t, w2, hh[j]);
            }
        }
        float hn0 = hh[0] * dv.x, hn1 = hh[1] * dv.y;
        float hn2 = hh[2] * dv.z, hn3 = hh[3] * dv.w;
        __half2 h01 = __floats2half2_rn(hn0, hn1);
        __half2 h23 = __floats2half2_rn(hn2, hn3);
        ((uint2*)g_hhnh)[i] = make_uint2(h2_as_u32(h01), h2_as_u32(h23));
        ((float4*)g_s2)[i] = make_float4(hn0 * dv.x, hn1 * dv.y, hn2 * dv.z, hn3 * dv.w);
    }
}

__global__ void k_node3(const float* __restrict__ b2c) {
    int i = blockIdx.x * blockDim.x + threadIdx.x;
    if (i == 0) g_fc2cnt = 0;   // reset fc2 completion counter each run
    if (i < NN4) {
        float b = __ldg(&b2c[0]);
        float4 dv = ((const float4*)g_dinv)[i];
        float4 s2 = ((const float4*)g_s2)[i];
        ((float4*)g_v)[i] = make_float4(
            lrelu(fmaf(dv.x, s2.x, b)),
            lrelu(fmaf(dv.y, s2.y, b)),
            lrelu(fmaf(dv.z, s2.z, b)),
            lrelu(fmaf(dv.w, s2.w, b)));
    }
}

// ---------------- edge kernels: 4 edges per thread via int4 ----------------
__global__ void k_deg(const int4* __restrict__ dst4, int E4) {
    int e = blockIdx.x * blockDim.x + threadIdx.x;
    if (e < E4) {
        int4 d = __ldcs(&dst4[e]);
        if ((unsigned)d.x < (unsigned)NN) atomicAdd(&g_degf[d.x], 1.0f);
        if ((unsigned)d.y < (unsigned)NN) atomicAdd(&g_degf[d.y], 1.0f);
        if ((unsigned)d.z < (unsigned)NN) atomicAdd(&g_degf[d.z], 1.0f);
        if ((unsigned)d.w < (unsigned)NN) atomicAdd(&g_degf[d.w], 1.0f);
    }
}

__global__ void k_scatter1(const int4* __restrict__ src4,
                           const int4* __restrict__ dst4, int E4) {
    int e = blockIdx.x * blockDim.x + threadIdx.x;
    if (e < E4) {
        int4 s = __ldcs(&src4[e]);
        int4 d = __ldcs(&dst4[e]);
        float vx = __half2float(g_xnh[s.x]);
        float vy = __half2float(g_xnh[s.y]);
        float vz = __half2float(g_xnh[s.z]);
        float vw = __half2float(g_xnh[s.w]);
        if ((unsigned)d.x < (unsigned)NN) atomicAdd(&g_s1[d.x], vx);
        if ((unsigned)d.y < (unsigned)NN) atomicAdd(&g_s1[d.y], vy);
        if ((unsigned)d.z < (unsigned)NN) atomicAdd(&g_s1[d.z], vz);
        if ((unsigned)d.w < (unsigned)NN) atomicAdd(&g_s1[d.w], vw);
    }
}

__global__ void k_scatter2(const int4* __restrict__ src4,
                           const int4* __restrict__ dst4, int E4) {
    int e = blockIdx.x * blockDim.x + threadIdx.x;
    if (e < E4) {
        int4 s = __ldcs(&src4[e]);
        int4 d = __ldcs(&dst4[e]);
        float vx = __half2float(g_hhnh[s.x]);
        float vy = __half2float(g_hhnh[s.y]);
        float vz = __half2float(g_hhnh[s.z]);
        float vw = __half2float(g_hhnh[s.w]);
        if ((unsigned)d.x < (unsigned)NN) atomicAdd(&g_s2[d.x], vx);
        if ((unsigned)d.y < (unsigned)NN) atomicAdd(&g_s2[d.y], vy);
        if ((unsigned)d.z < (unsigned)NN) atomicAdd(&g_s2[d.z], vz);
        if ((unsigned)d.w < (unsigned)NN) atomicAdd(&g_s2[d.w], vw);
    }
}

// ---------------- GEMV: 4 rows per block, 512 threads ----------------
__global__ void k_gemv(const float* __restrict__ Wf1,
                       const float* __restrict__ bf1) {
    const int r0 = blockIdx.x * 4;
    const int tid = threadIdx.x;     // 512 threads
    const float4* __restrict__ rowA = (const float4*)(Wf1 + (size_t)(r0 + 0) * NN);
    const float4* __restrict__ rowB = (const float4*)(Wf1 + (size_t)(r0 + 1) * NN);
    const float4* __restrict__ rowC = (const float4*)(Wf1 + (size_t)(r0 + 2) * NN);
    const float4* __restrict__ rowD = (const float4*)(Wf1 + (size_t)(r0 + 3) * NN);
    const float4* __restrict__ vv   = (const float4*)g_v;

    float sa = 0.f, sb = 0.f, sc = 0.f, sd = 0.f;
    for (int i = tid; i < NN4; i += 512) {
        float4 x  = vv[i];
        float4 wA = __ldcs(&rowA[i]);
        float4 wB = __ldcs(&rowB[i]);
        float4 wC = __ldcs(&rowC[i]);
        float4 wD = __ldcs(&rowD[i]);
        sa += wA.x*x.x + wA.y*x.y + wA.z*x.z + wA.w*x.w;
        sb += wB.x*x.x + wB.y*x.y + wB.z*x.z + wB.w*x.w;
        sc += wC.x*x.x + wC.y*x.y + wC.z*x.z + wC.w*x.w;
        sd += wD.x*x.x + wD.y*x.y + wD.z*x.z + wD.w*x.w;
    }

#pragma unroll
    for (int o = 16; o > 0; o >>= 1) {
        sa += __shfl_down_sync(0xFFFFFFFFu, sa, o);
        sb += __shfl_down_sync(0xFFFFFFFFu, sb, o);
        sc += __shfl_down_sync(0xFFFFFFFFu, sc, o);
        sd += __shfl_down_sync(0xFFFFFFFFu, sd, o);
    }
    __shared__ float redA[16], redB[16], redC[16], redD[16];
    int lane = tid & 31, wid = tid >> 5;   // 16 warps
    if (lane == 0) { redA[wid] = sa; redB[wid] = sb; redC[wid] = sc; redD[wid] = sd; }
    __syncthreads();
    if (wid == 0) {
        sa = (lane < 16) ? redA[lane] : 0.0f;
        sb = (lane < 16) ? redB[lane] : 0.0f;
        sc = (lane < 16) ? redC[lane] : 0.0f;
        sd = (lane < 16) ? redD[lane] : 0.0f;
#pragma unroll
        for (int o = 8; o > 0; o >>= 1) {
            sa += __shfl_down_sync(0xFFFFFFFFu, sa, o);
            sb += __shfl_down_sync(0xFFFFFFFFu, sb, o);
            sc += __shfl_down_sync(0xFFFFFFFFu, sc, o);
            sd += __shfl_down_sync(0xFFFFFFFFu, sd, o);
        }
        if (lane == 0) {
            g_z[r0 + 0] = lrelu(sa + __ldg(&bf1[r0 + 0]));
            g_z[r0 + 1] = lrelu(sb + __ldg(&bf1[r0 + 1]));
            g_z[r0 + 2] = lrelu(sc + __ldg(&bf1[r0 + 2]));
            g_z[r0 + 3] = lrelu(sd + __ldg(&bf1[r0 + 3]));
        }
    }
}

// ---------------- FC2 + fused log_softmax (last-block completes) ----------------
__global__ void k_fc2(const float* __restrict__ Wf2,
                      const float* __restrict__ bf2,
                      float* __restrict__ out) {
    const int o = blockIdx.x;          // 0..255
    const int tid = threadIdx.x;       // 128 threads
    const float4* __restrict__ row = (const float4*)(Wf2 + (size_t)o * HIDD);
    const float4* __restrict__ zz  = (const float4*)g_z;
    float s = 0.0f;
#pragma unroll
    for (int i = tid; i < HIDD / 4; i += 128) {   // 2 iterations
        float4 w = __ldg(&row[i]);
        float4 z = zz[i];
        s += w.x*z.x + w.y*z.y + w.z*z.z + w.w*z.w;
    }
#pragma unroll
    for (int off = 16; off > 0; off >>= 1)
        s += __shfl_down_sync(0xFFFFFFFFu, s, off);
    __shared__ float red[4];
    int lane = tid & 31, wid = tid >> 5;
    if (lane == 0) red[wid] = s;
    __syncthreads();
    __shared__ bool last;
    if (tid == 0) {
        float t = red[0] + red[1] + red[2] + red[3];
        g_logits[o] = t + __ldg(&bf2[o]);
        __threadfence();
        unsigned done = atomicAdd(&g_fc2cnt, 1u);
        last = (done == (unsigned)(gridDim.x - 1));
    }
    __syncthreads();
    if (!last) return;

    // ---- last block: log_softmax over 256 logits with 128 threads ----
    __shared__ float buf[128];
    float a0 = g_logits[tid];
    float a1 = g_logits[tid + 128];
    float m = fmaxf(a0, a1);
    buf[tid] = m;
    __syncthreads();
#pragma unroll
    for (int off = 64; off > 0; off >>= 1) {
        if (tid < off) buf[tid] = fmaxf(buf[tid], buf[tid + off]);
        __syncthreads();
    }
    float mx = buf[0];
    __syncthreads();
    buf[tid] = expf(a0 - mx) + expf(a1 - mx);
    __syncthreads();
#pragma unroll
    for (int off = 64; off > 0; off >>= 1) {
        if (tid < off) buf[tid] += buf[tid + off];
        __syncthreads();
    }
    float lse = mx + logf(buf[0]);
    out[tid]       = a0 - lse;
    out[tid + 128] = a1 - lse;
}

// ---------------- launch ----------------
extern "C" void kernel_launch(void* const* d_in, const int* in_sizes, int n_in,
                              void* d_out, int out_size) {
    const float* x   = (const float*)d_in[0];
    const int*   ei  = (const int*)d_in[1];     // int32 (jax downcast)
    const float* W1c = (const float*)d_in[2];
    const float* b1c = (const float*)d_in[3];
    const float* W2c = (const float*)d_in[4];
    const float* b2c = (const float*)d_in[5];
    const float* Wf1 = (const float*)d_in[6];
    const float* bf1 = (const float*)d_in[7];
    const float* Wf2 = (const float*)d_in[8];
    const float* bf2 = (const float*)d_in[9];
    float* out = (float*)d_out;

    const int E = in_sizes[1] / 2;              // 3,200,000
    const int E4 = E / 4;                       // 800,000
    const int4* src4 = (const int4*)ei;
    const int4* dst4 = (const int4*)(ei + E);

    const int TB = 256;
    const int nb_node4 = (NN4 + TB - 1) / TB;   // 98
    const int nb_edge4 = (E4 + TB - 1) / TB;

    // zero degrees via captured memset (no kernel launch)
    void* degp = nullptr;
    cudaGetSymbolAddress(&degp, g_degf);
    cudaMemsetAsync(degp, 0, NN * sizeof(float));

    k_deg<<<nb_edge4, TB>>>(dst4, E4);
    k_node1<<<nb_node4, TB>>>((const float4*)x);
    k_scatter1<<<nb_edge4, TB>>>(src4, dst4, E4);
    k_node2<<<nb_node4, TB>>>(W1c, b1c, W2c);
    k_scatter2<<<nb_edge4, TB>>>(src4, dst4, E4);
    k_node3<<<nb_node4, TB>>>(b2c);
    k_gemv<<<HIDD / 4, 512>>>(Wf1, bf1);
    k_fc2<<<OUTD, 128>>>(Wf2, bf2, out);
}

// round 15
// speedup vs baseline: 1.0354x; 1.0273x over previous
#include <cuda_runtime.h>
#include <cuda_fp16.h>
#include <math.h>

#define NN   100000
#define NN4  (NN / 4)        // 25000
#define CONV 16
#define HIDD 1024
#define OUTD 256

// ---------------- device scratch (no allocations allowed) ----------------
__device__ __align__(16) float  g_degf[NN];
__device__ __align__(16) float  g_dinv[NN];
__device__ __align__(16) float  g_s1[NN];      // conv1 accumulator (fp32 atomics)
__device__ __align__(16) __half g_xnh[NN];     // x[i]*dinv[i] as fp16 (L1-resident gathers)
__device__ __align__(16) float  g_s2[NN];      // conv2 accumulator
__device__ __align__(16) __half g_hhnh[NN];    // hh[i]*dinv[i] as fp16
__device__ __align__(16) float  g_v[NN];       // final node scalar
__device__ __align__(16) float  g_z[HIDD];     // hidden layer (post-lrelu)
__device__ __align__(16) float  g_logits[OUTD];
__device__ unsigned g_fc2cnt;                  // reset each run in node3

__device__ __forceinline__ float lrelu(float x) {
    return x >= 0.0f ? x : 0.01f * x;
}

__device__ __forceinline__ unsigned h2_as_u32(__half2 h) {
    return *reinterpret_cast<unsigned*>(&h);
}

// ---------------- node kernels (4 nodes per thread) ----------------
__global__ void k_node1(const float4* __restrict__ x4) {
    int i = blockIdx.x * blockDim.x + threadIdx.x;
    if (i < NN4) {
        float4 dg = ((const float4*)g_degf)[i];
        float4 xv = __ldg(&x4[i]);
        float d0 = rsqrtf(dg.x + 1.0f);
        float d1 = rsqrtf(dg.y + 1.0f);
        float d2 = rsqrtf(dg.z + 1.0f);
        float d3 = rsqrtf(dg.w + 1.0f);
        ((float4*)g_dinv)[i] = make_float4(d0, d1, d2, d3);
        float xn0 = xv.x * d0, xn1 = xv.y * d1, xn2 = xv.z * d2, xn3 = xv.w * d3;
        __half2 h01 = __floats2half2_rn(xn0, xn1);
        __half2 h23 = __floats2half2_rn(xn2, xn3);
        ((uint2*)g_xnh)[i] = make_uint2(h2_as_u32(h01), h2_as_u32(h23));
        ((float4*)g_s1)[i] = make_float4(xn0 * d0, xn1 * d1, xn2 * d2, xn3 * d3);
    }
}

__global__ void k_node2(const float* __restrict__ W1c,
                        const float* __restrict__ b1c,
                        const float* __restrict__ W2c) {
    int i = blockIdx.x * blockDim.x + threadIdx.x;
    if (i < NN4) {
        float4 dv = ((const float4*)g_dinv)[i];
        float4 s1 = ((const float4*)g_s1)[i];
        float a[4] = { dv.x * s1.x, dv.y * s1.y, dv.z * s1.z, dv.w * s1.w };
        float hh[4] = { 0.f, 0.f, 0.f, 0.f };
#pragma unroll
        for (int c = 0; c < CONV; c++) {
            float w1 = __ldg(&W1c[c]);
            float bb = __ldg(&b1c[c]);
            float w2 = __ldg(&W2c[c]);
#pragma unroll
            for (int j = 0; j < 4; j++) {
                float t = lrelu(fmaf(a[j], w1, bb));
                hh[j] = fmaf(t, w2, hh[j]);
            }
        }
        float hn0 = hh[0] * dv.x, hn1 = hh[1] * dv.y;
        float hn2 = hh[2] * dv.z, hn3 = hh[3] * dv.w;
        __half2 h01 = __floats2half2_rn(hn0, hn1);
        __half2 h23 = __floats2half2_rn(hn2, hn3);
        ((uint2*)g_hhnh)[i] = make_uint2(h2_as_u32(h01), h2_as_u32(h23));
        ((float4*)g_s2)[i] = make_float4(hn0 * dv.x, hn1 * dv.y, hn2 * dv.z, hn3 * dv.w);
    }
}

__global__ void k_node3(const float* __restrict__ b2c) {
    int i = blockIdx.x * blockDim.x + threadIdx.x;
    if (i == 0) g_fc2cnt = 0;   // reset fc2 completion counter each run
    if (i < NN4) {
        float b = __ldg(&b2c[0]);
        float4 dv = ((const float4*)g_dinv)[i];
        float4 s2 = ((const float4*)g_s2)[i];
        ((float4*)g_v)[i] = make_float4(
            lrelu(fmaf(dv.x, s2.x, b)),
            lrelu(fmaf(dv.y, s2.y, b)),
            lrelu(fmaf(dv.z, s2.z, b)),
            lrelu(fmaf(dv.w, s2.w, b)));
    }
}

// ---------------- edge kernels: 4 edges per thread via int4 ----------------
__global__ void k_deg(const int4* __restrict__ dst4, int E4) {
    int e = blockIdx.x * blockDim.x + threadIdx.x;
    if (e < E4) {
        int4 d = __ldcs(&dst4[e]);
        if ((unsigned)d.x < (unsigned)NN) atomicAdd(&g_degf[d.x], 1.0f);
        if ((unsigned)d.y < (unsigned)NN) atomicAdd(&g_degf[d.y], 1.0f);
        if ((unsigned)d.z < (unsigned)NN) atomicAdd(&g_degf[d.z], 1.0f);
        if ((unsigned)d.w < (unsigned)NN) atomicAdd(&g_degf[d.w], 1.0f);
    }
}

__global__ void k_scatter1(const int4* __restrict__ src4,
                           const int4* __restrict__ dst4, int E4) {
    int e = blockIdx.x * blockDim.x + threadIdx.x;
    if (e < E4) {
        int4 s = __ldcs(&src4[e]);
        int4 d = __ldcs(&dst4[e]);
        float vx = __half2float(g_xnh[s.x]);
        float vy = __half2float(g_xnh[s.y]);
        float vz = __half2float(g_xnh[s.z]);
        float vw = __half2float(g_xnh[s.w]);
        if ((unsigned)d.x < (unsigned)NN) atomicAdd(&g_s1[d.x], vx);
        if ((unsigned)d.y < (unsigned)NN) atomicAdd(&g_s1[d.y], vy);
        if ((unsigned)d.z < (unsigned)NN) atomicAdd(&g_s1[d.z], vz);
        if ((unsigned)d.w < (unsigned)NN) atomicAdd(&g_s1[d.w], vw);
    }
}

__global__ void k_scatter2(const int4* __restrict__ src4,
                           const int4* __restrict__ dst4, int E4) {
    int e = blockIdx.x * blockDim.x + threadIdx.x;
    if (e < E4) {
        int4 s = __ldcs(&src4[e]);
        int4 d = __ldcs(&dst4[e]);
        float vx = __half2float(g_hhnh[s.x]);
        float vy = __half2float(g_hhnh[s.y]);
        float vz = __half2float(g_hhnh[s.z]);
        float vw = __half2float(g_hhnh[s.w]);
        if ((unsigned)d.x < (unsigned)NN) atomicAdd(&g_s2[d.x], vx);
        if ((unsigned)d.y < (unsigned)NN) atomicAdd(&g_s2[d.y], vy);
        if ((unsigned)d.z < (unsigned)NN) atomicAdd(&g_s2[d.z], vz);
        if ((unsigned)d.w < (unsigned)NN) atomicAdd(&g_s2[d.w], vw);
    }
}

// ---------------- GEMV: 4 rows per block, 512 threads ----------------
__global__ void k_gemv(const float* __restrict__ Wf1,
                       const float* __restrict__ bf1) {
    const int r0 = blockIdx.x * 4;
    const int tid = threadIdx.x;     // 512 threads
    const float4* __restrict__ rowA = (const float4*)(Wf1 + (size_t)(r0 + 0) * NN);
    const float4* __restrict__ rowB = (const float4*)(Wf1 + (size_t)(r0 + 1) * NN);
    const float4* __restrict__ rowC = (const float4*)(Wf1 + (size_t)(r0 + 2) * NN);
    const float4* __restrict__ rowD = (const float4*)(Wf1 + (size_t)(r0 + 3) * NN);
    const float4* __restrict__ vv   = (const float4*)g_v;

    float sa = 0.f, sb = 0.f, sc = 0.f, sd = 0.f;
    for (int i = tid; i < NN4; i += 512) {
        float4 x  = vv[i];
        float4 wA = __ldcs(&rowA[i]);
        float4 wB = __ldcs(&rowB[i]);
        float4 wC = __ldcs(&rowC[i]);
        float4 wD = __ldcs(&rowD[i]);
        sa += wA.x*x.x + wA.y*x.y + wA.z*x.z + wA.w*x.w;
        sb += wB.x*x.x + wB.y*x.y + wB.z*x.z + wB.w*x.w;
        sc += wC.x*x.x + wC.y*x.y + wC.z*x.z + wC.w*x.w;
        sd += wD.x*x.x + wD.y*x.y + wD.z*x.z + wD.w*x.w;
    }

#pragma unroll
    for (int o = 16; o > 0; o >>= 1) {
        sa += __shfl_down_sync(0xFFFFFFFFu, sa, o);
        sb += __shfl_down_sync(0xFFFFFFFFu, sb, o);
        sc += __shfl_down_sync(0xFFFFFFFFu, sc, o);
        sd += __shfl_down_sync(0xFFFFFFFFu, sd, o);
    }
    __shared__ float redA[16], redB[16], redC[16], redD[16];
    int lane = tid & 31, wid = tid >> 5;   // 16 warps
    if (lane == 0) { redA[wid] = sa; redB[wid] = sb; redC[wid] = sc; redD[wid] = sd; }
    __syncthreads();
    if (wid == 0) {
        sa = (lane < 16) ? redA[lane] : 0.0f;
        sb = (lane < 16) ? redB[lane] : 0.0f;
        sc = (lane < 16) ? redC[lane] : 0.0f;
        sd = (lane < 16) ? redD[lane] : 0.0f;
#pragma unroll
        for (int o = 8; o > 0; o >>= 1) {
            sa += __shfl_down_sync(0xFFFFFFFFu, sa, o);
            sb += __shfl_down_sync(0xFFFFFFFFu, sb, o);
            sc += __shfl_down_sync(0xFFFFFFFFu, sc, o);
            sd += __shfl_down_sync(0xFFFFFFFFu, sd, o);
        }
        if (lane == 0) {
            g_z[r0 + 0] = lrelu(sa + __ldg(&bf1[r0 + 0]));
            g_z[r0 + 1] = lrelu(sb + __ldg(&bf1[r0 + 1]));
            g_z[r0 + 2] = lrelu(sc + __ldg(&bf1[r0 + 2]));
            g_z[r0 + 3] = lrelu(sd + __ldg(&bf1[r0 + 3]));
        }
    }
}

// ---------------- FC2 + fused log_softmax (last-block completes) ----------------
__global__ void k_fc2(const float* __restrict__ Wf2,
                      const float* __restrict__ bf2,
                      float* __restrict__ out) {
    const int o = blockIdx.x;          // 0..255
    const int tid = threadIdx.x;       // 128 threads
    const float4* __restrict__ row = (const float4*)(Wf2 + (size_t)o * HIDD);
    const float4* __restrict__ zz  = (const float4*)g_z;
    float s = 0.0f;
#pragma unroll
    for (int i = tid; i < HIDD / 4; i += 128) {   // 2 iterations
        float4 w = __ldg(&row[i]);
        float4 z = zz[i];
        s += w.x*z.x + w.y*z.y + w.z*z.z + w.w*z.w;
    }
#pragma unroll
    for (int off = 16; off > 0; off >>= 1)
        s += __shfl_down_sync(0xFFFFFFFFu, s, off);
    __shared__ float red[4];
    int lane = tid & 31, wid = tid >> 5;
    if (lane == 0) red[wid] = s;
    __syncthreads();
    __shared__ bool last;
    if (tid == 0) {
        float t = red[0] + red[1] + red[2] + red[3];
        g_logits[o] = t + __ldg(&bf2[o]);
        __threadfence();
        unsigned done = atomicAdd(&g_fc2cnt, 1u);
        last = (done == (unsigned)(gridDim.x - 1));
    }
    __syncthreads();
    if (!last) return;

    // ---- last block: log_softmax over 256 logits with 128 threads ----
    __shared__ float buf[128];
    float a0 = g_logits[tid];
    float a1 = g_logits[tid + 128];
    float m = fmaxf(a0, a1);
    buf[tid] = m;
    __syncthreads();
#pragma unroll
    for (int off = 64; off > 0; off >>= 1) {
        if (tid < off) buf[tid] = fmaxf(buf[tid], buf[tid + off]);
        __syncthreads();
    }
    float mx = buf[0];
    __syncthreads();
    buf[tid] = expf(a0 - mx) + expf(a1 - mx);
    __syncthreads();
#pragma unroll
    for (int off = 64; off > 0; off >>= 1) {
        if (tid < off) buf[tid] += buf[tid + off];
        __syncthreads();
    }
    float lse = mx + logf(buf[0]);
    out[tid]       = a0 - lse;
    out[tid + 128] = a1 - lse;
}

// ---------------- launch ----------------
extern "C" void kernel_launch(void* const* d_in, const int* in_sizes, int n_in,
                              void* d_out, int out_size) {
    const float* x   = (const float*)d_in[0];
    const int*   ei  = (const int*)d_in[1];     // int32 (jax downcast)
    const float* W1c = (const float*)d_in[2];
    const float* b1c = (const float*)d_in[3];
    const float* W2c = (const float*)d_in[4];
    const float* b2c = (const float*)d_in[5];
    const float* Wf1 = (const float*)d_in[6];
    const float* bf1 = (const float*)d_in[7];
    const float* Wf2 = (const float*)d_in[8];
    const float* bf2 = (const float*)d_in[9];
    float* out = (float*)d_out;

    const int E = in_sizes[1] / 2;              // 3,200,000
    const int E4 = E / 4;                       // 800,000
    const int4* src4 = (const int4*)ei;
    const int4* dst4 = (const int4*)(ei + E);

    const int TB = 256;
    const int nb_node4 = (NN4 + TB - 1) / TB;   // 98
    const int nb_edge4 = (E4 + TB - 1) / TB;

    // zero degrees via captured memset (no kernel launch)
    void* degp = nullptr;
    cudaGetSymbolAddress(&degp, g_degf);
    cudaMemsetAsync(degp, 0, NN * sizeof(float));

    k_deg<<<nb_edge4, TB>>>(dst4, E4);
    k_node1<<<nb_node4, TB>>>((const float4*)x);
    k_scatter1<<<nb_edge4, TB>>>(src4, dst4, E4);
    k_node2<<<nb_node4, TB>>>(W1c, b1c, W2c);
    k_scatter2<<<nb_edge4, TB>>>(src4, dst4, E4);
    k_node3<<<nb_node4, TB>>>(b2c);
    k_gemv<<<HIDD / 4, 512>>>(Wf1, bf1);
    k_fc2<<<OUTD, 128>>>(Wf2, bf2, out);
}